// round 13
// baseline (speedup 1.0000x reference)
#include <cuda_runtime.h>

#define HH 8
#define BB 2
#define LL 256
#define DD 512
#define DK 64
#define BH (BB*HH)

__device__ float g_q[BH*LL*DK];
__device__ float g_k[BH*LL*DK];
__device__ float g_v[BH*LL*DK];
__device__ float g_ctx[BH*LL*DK];

__device__ __forceinline__ unsigned f2tf32(float x) {
    unsigned r; asm("cvt.rna.tf32.f32 %0, %1;" : "=r"(r) : "f"(x)); return r;
}
__device__ __forceinline__ uint4 cvt4(float4 v) {
    uint4 u; u.x = f2tf32(v.x); u.y = f2tf32(v.y); u.z = f2tf32(v.z); u.w = f2tf32(v.w);
    return u;
}

#define KT 32
#define NCH (DD / KT)   // 16 k-chunks

// ---------------------------------------------------------------------------
// Fused Q/K/V projection, tf32 tensor cores. MT=16 x NT=64 x KT=32 tiles;
// 128 threads = 4 warps (1M x 4N), warp tile 16x16 (2x m16n8k8 per k-step).
// Grid (8,32,3) = 768 CTAs -> ~21 warps/SM (was 10) to hide chunk-loop
// latency. cvt to tf32 at smem-store time. Y = X @ W^T + b -> [B*H, L, dk].
// ---------------------------------------------------------------------------
__global__ void __launch_bounds__(128) proj_kernel(
    const float* __restrict__ q_in, const float* __restrict__ k_in,
    const float* __restrict__ v_in,
    const float* __restrict__ Wq, const float* __restrict__ bq,
    const float* __restrict__ Wk, const float* __restrict__ bk,
    const float* __restrict__ Wv, const float* __restrict__ bv)
{
    const int which = blockIdx.z;
    const float* X    = which == 0 ? q_in : (which == 1 ? k_in : v_in);
    const float* W    = which == 0 ? Wq   : (which == 1 ? Wk   : Wv);
    const float* bias = which == 0 ? bq   : (which == 1 ? bk   : bv);
    float*       Y    = which == 0 ? g_q  : (which == 1 ? g_k  : g_v);

    __shared__ unsigned Xs[2][16][KT + 4];
    __shared__ unsigned Ws[2][64][KT + 4];

    const int tid  = threadIdx.x;
    const int warp = tid >> 5;        // = wn (0..3)
    const int lane = tid & 31;
    const int g  = lane >> 2;
    const int t  = lane & 3;

    const int m0 = blockIdx.y * 16;
    const int n0 = blockIdx.x * 64;

    // loaders: X 16x32 (1 float4/thread), W 64x32 (4 float4/thread)
    const int xr = tid >> 3, xc = tid & 7;            // X col quad xc
    const int wr = tid >> 1, wh = (tid & 1) * 16;     // W cols wh..wh+15
    const float* Xp = &X[(size_t)(m0 + xr) * DD + xc * 4];
    const float* Wp = &W[(size_t)(n0 + wr) * DD + wh];

    float4 px0 = *(const float4*)(Xp);
    float4 pw0 = *(const float4*)(Wp);
    float4 pw1 = *(const float4*)(Wp + 4);
    float4 pw2 = *(const float4*)(Wp + 8);
    float4 pw3 = *(const float4*)(Wp + 12);

    float c[2][4];
    #pragma unroll
    for (int j = 0; j < 2; j++)
        #pragma unroll
        for (int q = 0; q < 4; q++) c[j][q] = 0.f;

    #pragma unroll 1
    for (int ch = 0; ch < NCH; ch++) {
        const int cur = ch & 1;
        *(uint4*)&Xs[cur][xr][xc * 4]  = cvt4(px0);
        *(uint4*)&Ws[cur][wr][wh]      = cvt4(pw0);
        *(uint4*)&Ws[cur][wr][wh + 4]  = cvt4(pw1);
        *(uint4*)&Ws[cur][wr][wh + 8]  = cvt4(pw2);
        *(uint4*)&Ws[cur][wr][wh + 12] = cvt4(pw3);
        __syncthreads();

        if (ch + 1 < NCH) {
            const int k0n = (ch + 1) * KT;
            px0 = *(const float4*)(Xp + k0n);
            pw0 = *(const float4*)(Wp + k0n);
            pw1 = *(const float4*)(Wp + k0n + 4);
            pw2 = *(const float4*)(Wp + k0n + 8);
            pw3 = *(const float4*)(Wp + k0n + 12);
        }

        #pragma unroll
        for (int ks = 0; ks < 4; ks++) {
            const int K = ks * 8;
            const unsigned a0 = Xs[cur][g][K + t];
            const unsigned a1 = Xs[cur][8 + g][K + t];
            const unsigned a2 = Xs[cur][g][K + t + 4];
            const unsigned a3 = Xs[cur][8 + g][K + t + 4];
            #pragma unroll
            for (int j = 0; j < 2; j++) {
                const int nb = warp * 16 + j * 8;
                const unsigned b0 = Ws[cur][nb + g][K + t];
                const unsigned b1 = Ws[cur][nb + g][K + t + 4];
                asm volatile(
                    "mma.sync.aligned.m16n8k8.row.col.f32.tf32.tf32.f32 "
                    "{%0,%1,%2,%3}, {%4,%5,%6,%7}, {%8,%9}, {%0,%1,%2,%3};"
                    : "+f"(c[j][0]), "+f"(c[j][1]), "+f"(c[j][2]), "+f"(c[j][3])
                    : "r"(a0), "r"(a1), "r"(a2), "r"(a3), "r"(b0), "r"(b1));
            }
        }
        __syncthreads();
    }

    // Epilogue: scatter into [B*H, L, dk]; NT=64 aligned -> one head per CTA.
    const int h = n0 >> 6;
    const int row0 = m0 + g;
    const int b0i = row0 >> 8, l0 = row0 & 255;
    const int row1 = row0 + 8;
    const int b1i = row1 >> 8, l1 = row1 & 255;
    #pragma unroll
    for (int j = 0; j < 2; j++) {
        const int col = n0 + warp * 16 + j * 8 + 2 * t;
        const int d = col & 63;
        const float bx = bias[col], by = bias[col + 1];
        *(float2*)&Y[((size_t)(b0i * HH + h) * LL + l0) * DK + d] =
            make_float2(c[j][0] + bx, c[j][1] + by);
        *(float2*)&Y[((size_t)(b1i * HH + h) * LL + l1) * DK + d] =
            make_float2(c[j][2] + bx, c[j][3] + by);
    }
}

// ---------------------------------------------------------------------------
// Attention core (R12, unchanged): G=4 query rows per CTA; half-warp per j;
// rq/rv streamed __ldcs; unroll 2.
// ---------------------------------------------------------------------------
#define G 4
__global__ void __launch_bounds__(256) attn_kernel(
    const int* __restrict__ mask,
    const float* __restrict__ rq,
    const float* __restrict__ rv)
{
    const int i0 = blockIdx.x * G;
    const int bh = blockIdx.y;
    const int b  = bh >> 3;
    const int tid  = threadIdx.x;
    const int warp = tid >> 5;
    const int lane = tid & 31;
    const int half = lane >> 4;
    const int lq   = lane & 15;

    __shared__ float sc[G][LL];
    __shared__ float cpart[16][G][DK + 4];
    __shared__ float wred[8];

    const float scale = 0.125f;
    const size_t kvbase = (size_t)bh * LL * DK;
    const size_t rrow   = ((size_t)bh * LL + i0) * (size_t)(LL * DK);

    float4 q4[G];
    #pragma unroll
    for (int g = 0; g < G; g++)
        q4[g] = *(const float4*)&g_q[kvbase + (size_t)(i0 + g) * DK + lq * 4];

    #pragma unroll 2
    for (int it = 0; it < 16; it++) {
        const int j = it * 16 + warp * 2 + half;
        float4 k4 = *(const float4*)&g_k[kvbase + (size_t)j * DK + lq * 4];
        k4.x *= scale; k4.y *= scale; k4.z *= scale; k4.w *= scale;
        float p[G];
        #pragma unroll
        for (int g = 0; g < G; g++) {
            const float4 r4 = __ldcs((const float4*)&rq[rrow + (size_t)(g * (LL * DK) + j * DK) + lq * 4]);
            p[g] = q4[g].x * (k4.x + r4.x) + q4[g].y * (k4.y + r4.y)
                 + q4[g].z * (k4.z + r4.z) + q4[g].w * (k4.w + r4.w);
        }
        #pragma unroll
        for (int g = 0; g < G; g++) {
            p[g] += __shfl_down_sync(0xffffffffu, p[g], 8, 16);
            p[g] += __shfl_down_sync(0xffffffffu, p[g], 4, 16);
            p[g] += __shfl_down_sync(0xffffffffu, p[g], 2, 16);
            p[g] += __shfl_down_sync(0xffffffffu, p[g], 1, 16);
        }
        if (lq == 0) {
            #pragma unroll
            for (int g = 0; g < G; g++) sc[g][j] = p[g];
        }
    }
    __syncthreads();

    {
        const int r   = warp >> 1;
        const int sub = warp & 1;
        const int mbase = (b * LL + i0 + r) * LL + sub * 128 + lane;
        float s[4];
        #pragma unroll
        for (int k = 0; k < 4; k++) {
            float v = sc[r][sub * 128 + lane + 32 * k];
            if (mask[mbase + 32 * k] == 0) v = -1e9f;
            s[k] = v;
        }
        float m = fmaxf(fmaxf(s[0], s[1]), fmaxf(s[2], s[3]));
        #pragma unroll
        for (int off = 16; off > 0; off >>= 1)
            m = fmaxf(m, __shfl_xor_sync(0xffffffffu, m, off));
        if (lane == 0) wred[warp] = m;
        __syncthreads();
        const float rowmax = fmaxf(wred[2 * r], wred[2 * r + 1]);
        float e0v = __expf(s[0] - rowmax), e1v = __expf(s[1] - rowmax);
        float e2v = __expf(s[2] - rowmax), e3v = __expf(s[3] - rowmax);
        float sum = e0v + e1v + e2v + e3v;
        #pragma unroll
        for (int off = 16; off > 0; off >>= 1)
            sum += __shfl_xor_sync(0xffffffffu, sum, off);
        __syncthreads();
        if (lane == 0) wred[warp] = sum;
        __syncthreads();
        const float inv = 1.0f / (wred[2 * r] + wred[2 * r + 1]);
        sc[r][sub * 128 + lane +  0] = e0v * inv;
        sc[r][sub * 128 + lane + 32] = e1v * inv;
        sc[r][sub * 128 + lane + 64] = e2v * inv;
        sc[r][sub * 128 + lane + 96] = e3v * inv;
    }
    __syncthreads();

    float4 acc[G];
    #pragma unroll
    for (int g = 0; g < G; g++) acc[g] = make_float4(0.f, 0.f, 0.f, 0.f);

    #pragma unroll 2
    for (int it = 0; it < 16; it++) {
        const int j = it * 16 + warp * 2 + half;
        const float4 v4 = *(const float4*)&g_v[kvbase + (size_t)j * DK + lq * 4];
        #pragma unroll
        for (int g = 0; g < G; g++) {
            const float4 r4 = __ldcs((const float4*)&rv[rrow + (size_t)(g * (LL * DK) + j * DK) + lq * 4]);
            const float pj = sc[g][j];
            acc[g].x += pj * (v4.x + r4.x);
            acc[g].y += pj * (v4.y + r4.y);
            acc[g].z += pj * (v4.z + r4.z);
            acc[g].w += pj * (v4.w + r4.w);
        }
    }
    #pragma unroll
    for (int g = 0; g < G; g++)
        *(float4*)&cpart[warp * 2 + half][g][lq * 4] = acc[g];
    __syncthreads();

    {
        const int g = tid >> 6, d = tid & 63;
        float ssum = 0.f;
        #pragma unroll
        for (int p = 0; p < 16; p++) ssum += cpart[p][g][d];
        g_ctx[kvbase + (size_t)(i0 + g) * DK + d] = ssum;
    }
}

// ---------------------------------------------------------------------------
// Output projection (R12 fp32, unchanged): 32x64x32, 128 threads, 4x4/thread,
// double-buffered; gathers ctx; out = ctx @ Wo^T + bo.
// ---------------------------------------------------------------------------
#define PBK 32
#define NKT (DD / PBK)

__global__ void __launch_bounds__(128) out_kernel(
    const float* __restrict__ Wo, const float* __restrict__ bo,
    float* __restrict__ out)
{
    __shared__ float Xs[2][PBK][32 + 4];
    __shared__ float Ws[2][PBK][64 + 4];

    const int tid = threadIdx.x;
    const int tx = tid & 15;
    const int ty = tid >> 4;
    const int m0 = blockIdx.y * 32;
    const int n0 = blockIdx.x * 64;

    const int xr = tid >> 2, xc4 = tid & 3;
    const int wr0 = tid >> 1, wc4_0 = (tid & 1) * 2;

    const int mm = m0 + xr;
    const int bb = mm >> 8, l = mm & 255;
    const float* Wp = &Wo[(size_t)(n0 + wr0) * DD + wc4_0 * 4];

    float4 px0, px1, pw0, pw1, pw2, pw3;
    {
        int c0 = xc4 * 4;       int h0 = c0 >> 6, d0 = c0 & 63;
        int c1 = 16 + xc4 * 4;  int h1 = c1 >> 6, d1 = c1 & 63;
        px0 = *(const float4*)&g_ctx[((size_t)(bb * HH + h0) * LL + l) * DK + d0];
        px1 = *(const float4*)&g_ctx[((size_t)(bb * HH + h1) * LL + l) * DK + d1];
    }
    pw0 = *(const float4*)(Wp);
    pw1 = *(const float4*)(Wp + 4);
    pw2 = *(const float4*)(Wp + 16);
    pw3 = *(const float4*)(Wp + 20);

    float4 acc0 = {0,0,0,0}, acc1 = {0,0,0,0}, acc2 = {0,0,0,0}, acc3 = {0,0,0,0};

    #pragma unroll 1
    for (int t = 0; t < NKT; t++) {
        const int cur = t & 1;
        Xs[cur][xc4*4+0][xr] = px0.x; Xs[cur][xc4*4+1][xr] = px0.y;
        Xs[cur][xc4*4+2][xr] = px0.z; Xs[cur][xc4*4+3][xr] = px0.w;
        Xs[cur][16+xc4*4+0][xr] = px1.x; Xs[cur][16+xc4*4+1][xr] = px1.y;
        Xs[cur][16+xc4*4+2][xr] = px1.z; Xs[cur][16+xc4*4+3][xr] = px1.w;
        Ws[cur][wc4_0*4+0][wr0] = pw0.x; Ws[cur][wc4_0*4+1][wr0] = pw0.y;
        Ws[cur][wc4_0*4+2][wr0] = pw0.z; Ws[cur][wc4_0*4+3][wr0] = pw0.w;
        Ws[cur][wc4_0*4+4][wr0] = pw1.x; Ws[cur][wc4_0*4+5][wr0] = pw1.y;
        Ws[cur][wc4_0*4+6][wr0] = pw1.z; Ws[cur][wc4_0*4+7][wr0] = pw1.w;
        Ws[cur][16+wc4_0*4+0][wr0] = pw2.x; Ws[cur][16+wc4_0*4+1][wr0] = pw2.y;
        Ws[cur][16+wc4_0*4+2][wr0] = pw2.z; Ws[cur][16+wc4_0*4+3][wr0] = pw2.w;
        Ws[cur][16+wc4_0*4+4][wr0] = pw3.x; Ws[cur][16+wc4_0*4+5][wr0] = pw3.y;
        Ws[cur][16+wc4_0*4+6][wr0] = pw3.z; Ws[cur][16+wc4_0*4+7][wr0] = pw3.w;
        __syncthreads();

        if (t + 1 < NKT) {
            const int k0n = (t + 1) * PBK;
            int c0 = k0n + xc4 * 4;       int h0 = c0 >> 6, d0 = c0 & 63;
            int c1 = k0n + 16 + xc4 * 4;  int h1 = c1 >> 6, d1 = c1 & 63;
            px0 = *(const float4*)&g_ctx[((size_t)(bb * HH + h0) * LL + l) * DK + d0];
            px1 = *(const float4*)&g_ctx[((size_t)(bb * HH + h1) * LL + l) * DK + d1];
            pw0 = *(const float4*)(Wp + k0n);
            pw1 = *(const float4*)(Wp + k0n + 4);
            pw2 = *(const float4*)(Wp + k0n + 16);
            pw3 = *(const float4*)(Wp + k0n + 20);
        }

        #pragma unroll
        for (int kk = 0; kk < PBK; kk++) {
            float4 a = *(const float4*)&Xs[cur][kk][ty * 4];
            float4 b = *(const float4*)&Ws[cur][kk][tx * 4];
            acc0.x += a.x*b.x; acc0.y += a.x*b.y; acc0.z += a.x*b.z; acc0.w += a.x*b.w;
            acc1.x += a.y*b.x; acc1.y += a.y*b.y; acc1.z += a.y*b.z; acc1.w += a.y*b.w;
            acc2.x += a.z*b.x; acc2.y += a.z*b.y; acc2.z += a.z*b.z; acc2.w += a.z*b.w;
            acc3.x += a.w*b.x; acc3.y += a.w*b.y; acc3.z += a.w*b.z; acc3.w += a.w*b.w;
        }
        __syncthreads();
    }

    const int e0 = n0 + tx * 4;
    float4 b4 = *(const float4*)&bo[e0];
    float4 accs[4] = {acc0, acc1, acc2, acc3};
    #pragma unroll
    for (int i = 0; i < 4; i++) {
        int m = m0 + ty * 4 + i;
        float4 o;
        o.x = accs[i].x + b4.x; o.y = accs[i].y + b4.y;
        o.z = accs[i].z + b4.z; o.w = accs[i].w + b4.w;
        *(float4*)&out[(size_t)m * DD + e0] = o;
    }
}

extern "C" void kernel_launch(void* const* d_in, const int* in_sizes, int n_in,
                              void* d_out, int out_size)
{
    const float* query = (const float*)d_in[0];
    const float* key   = (const float*)d_in[1];
    const float* value = (const float*)d_in[2];
    const int*   mask  = (const int*)d_in[3];
    const float* rq    = (const float*)d_in[4];
    const float* rv    = (const float*)d_in[5];
    const float* Wq    = (const float*)d_in[6];
    const float* bq    = (const float*)d_in[7];
    const float* Wk    = (const float*)d_in[8];
    const float* bk    = (const float*)d_in[9];
    const float* Wv    = (const float*)d_in[10];
    const float* bv    = (const float*)d_in[11];
    const float* Wo    = (const float*)d_in[12];
    const float* bo    = (const float*)d_in[13];
    float* out = (float*)d_out;

    proj_kernel<<<dim3(DD / 64, (BB * LL) / 16, 3), 128>>>(
        query, key, value, Wq, bq, Wk, bk, Wv, bv);
    attn_kernel<<<dim3(LL / G, BH), 256>>>(mask, rq, rv);
    out_kernel<<<dim3(DD / 64, (BB * LL) / 32), 128>>>(Wo, bo, out);
}

// round 14
// speedup vs baseline: 1.0571x; 1.0571x over previous
#include <cuda_runtime.h>

#define HH 8
#define BB 2
#define LL 256
#define DD 512
#define DK 64
#define BH (BB*HH)

__device__ float g_q[BH*LL*DK];
__device__ float g_k[BH*LL*DK];
__device__ float g_v[BH*LL*DK];
__device__ float g_ctx[BH*LL*DK];

__device__ __forceinline__ unsigned f2tf32(float x) {
    unsigned r; asm("cvt.rna.tf32.f32 %0, %1;" : "=r"(r) : "f"(x)); return r;
}
__device__ __forceinline__ uint4 cvt4(float4 v) {
    uint4 u; u.x = f2tf32(v.x); u.y = f2tf32(v.y); u.z = f2tf32(v.z); u.w = f2tf32(v.w);
    return u;
}

#define KT 32
#define NCH (DD / KT)   // 16 k-chunks

// ---------------------------------------------------------------------------
// Fused Q/K/V projection, tf32 tensor cores (R12 exact — measured best).
// MT=32 x NT=64 x KT=32; 128 threads = 4 warps (2M x 2N); cvt at store time.
// Grid (8,16,3) = 384 CTAs. Y = X @ W^T + b -> [B*H, L, dk].
// ---------------------------------------------------------------------------
__global__ void __launch_bounds__(128) proj_kernel(
    const float* __restrict__ q_in, const float* __restrict__ k_in,
    const float* __restrict__ v_in,
    const float* __restrict__ Wq, const float* __restrict__ bq,
    const float* __restrict__ Wk, const float* __restrict__ bk,
    const float* __restrict__ Wv, const float* __restrict__ bv)
{
    const int which = blockIdx.z;
    const float* X    = which == 0 ? q_in : (which == 1 ? k_in : v_in);
    const float* W    = which == 0 ? Wq   : (which == 1 ? Wk   : Wv);
    const float* bias = which == 0 ? bq   : (which == 1 ? bk   : bv);
    float*       Y    = which == 0 ? g_q  : (which == 1 ? g_k  : g_v);

    __shared__ unsigned Xs[2][32][KT + 4];
    __shared__ unsigned Ws[2][64][KT + 4];

    const int tid  = threadIdx.x;
    const int warp = tid >> 5;
    const int lane = tid & 31;
    const int wm = warp & 1;
    const int wn = warp >> 1;
    const int g  = lane >> 2;
    const int t  = lane & 3;

    const int m0 = blockIdx.y * 32;
    const int n0 = blockIdx.x * 64;

    const int xr = tid >> 2, xc = tid & 3;
    const int wr = tid >> 1, wh = (tid & 1) * 16;
    const float* Xp = &X[(size_t)(m0 + xr) * DD + xc * 4];
    const float* Wp = &W[(size_t)(n0 + wr) * DD + wh];

    float4 px0 = *(const float4*)(Xp);
    float4 px1 = *(const float4*)(Xp + 16);
    float4 pw0 = *(const float4*)(Wp);
    float4 pw1 = *(const float4*)(Wp + 4);
    float4 pw2 = *(const float4*)(Wp + 8);
    float4 pw3 = *(const float4*)(Wp + 12);

    float c[4][4];
    #pragma unroll
    for (int j = 0; j < 4; j++)
        #pragma unroll
        for (int q = 0; q < 4; q++) c[j][q] = 0.f;

    #pragma unroll 1
    for (int ch = 0; ch < NCH; ch++) {
        const int cur = ch & 1;
        *(uint4*)&Xs[cur][xr][xc * 4]      = cvt4(px0);
        *(uint4*)&Xs[cur][xr][16 + xc * 4] = cvt4(px1);
        *(uint4*)&Ws[cur][wr][wh]          = cvt4(pw0);
        *(uint4*)&Ws[cur][wr][wh + 4]      = cvt4(pw1);
        *(uint4*)&Ws[cur][wr][wh + 8]      = cvt4(pw2);
        *(uint4*)&Ws[cur][wr][wh + 12]     = cvt4(pw3);
        __syncthreads();

        if (ch + 1 < NCH) {
            const int k0n = (ch + 1) * KT;
            px0 = *(const float4*)(Xp + k0n);
            px1 = *(const float4*)(Xp + k0n + 16);
            pw0 = *(const float4*)(Wp + k0n);
            pw1 = *(const float4*)(Wp + k0n + 4);
            pw2 = *(const float4*)(Wp + k0n + 8);
            pw3 = *(const float4*)(Wp + k0n + 12);
        }

        const int ar = wm * 16;
        #pragma unroll
        for (int ks = 0; ks < 4; ks++) {
            const int K = ks * 8;
            const unsigned a0 = Xs[cur][ar + g][K + t];
            const unsigned a1 = Xs[cur][ar + 8 + g][K + t];
            const unsigned a2 = Xs[cur][ar + g][K + t + 4];
            const unsigned a3 = Xs[cur][ar + 8 + g][K + t + 4];
            #pragma unroll
            for (int j = 0; j < 4; j++) {
                const int nb = wn * 32 + j * 8;
                const unsigned b0 = Ws[cur][nb + g][K + t];
                const unsigned b1 = Ws[cur][nb + g][K + t + 4];
                asm volatile(
                    "mma.sync.aligned.m16n8k8.row.col.f32.tf32.tf32.f32 "
                    "{%0,%1,%2,%3}, {%4,%5,%6,%7}, {%8,%9}, {%0,%1,%2,%3};"
                    : "+f"(c[j][0]), "+f"(c[j][1]), "+f"(c[j][2]), "+f"(c[j][3])
                    : "r"(a0), "r"(a1), "r"(a2), "r"(a3), "r"(b0), "r"(b1));
            }
        }
        __syncthreads();
    }

    const int h = n0 >> 6;
    const int row0 = m0 + wm * 16 + g;
    const int b0i = row0 >> 8, l0 = row0 & 255;
    const int row1 = row0 + 8;
    const int b1i = row1 >> 8, l1 = row1 & 255;
    #pragma unroll
    for (int j = 0; j < 4; j++) {
        const int col = n0 + wn * 32 + j * 8 + 2 * t;
        const int d = col & 63;
        const float bx = bias[col], by = bias[col + 1];
        *(float2*)&Y[((size_t)(b0i * HH + h) * LL + l0) * DK + d] =
            make_float2(c[j][0] + bx, c[j][1] + by);
        *(float2*)&Y[((size_t)(b1i * HH + h) * LL + l1) * DK + d] =
            make_float2(c[j][2] + bx, c[j][3] + by);
    }
}

// ---------------------------------------------------------------------------
// Attention core: G=4 query rows per CTA; half-warp per j; rq/rv streamed
// __ldcs; unroll 3 (ONLY change vs R12: deeper MLP, ~15 loads in flight).
// ---------------------------------------------------------------------------
#define G 4
__global__ void __launch_bounds__(256) attn_kernel(
    const int* __restrict__ mask,
    const float* __restrict__ rq,
    const float* __restrict__ rv)
{
    const int i0 = blockIdx.x * G;
    const int bh = blockIdx.y;
    const int b  = bh >> 3;
    const int tid  = threadIdx.x;
    const int warp = tid >> 5;
    const int lane = tid & 31;
    const int half = lane >> 4;
    const int lq   = lane & 15;

    __shared__ float sc[G][LL];
    __shared__ float cpart[16][G][DK + 4];
    __shared__ float wred[8];

    const float scale = 0.125f;
    const size_t kvbase = (size_t)bh * LL * DK;
    const size_t rrow   = ((size_t)bh * LL + i0) * (size_t)(LL * DK);

    float4 q4[G];
    #pragma unroll
    for (int g = 0; g < G; g++)
        q4[g] = *(const float4*)&g_q[kvbase + (size_t)(i0 + g) * DK + lq * 4];

    #pragma unroll 3
    for (int it = 0; it < 16; it++) {
        const int j = it * 16 + warp * 2 + half;
        float4 k4 = *(const float4*)&g_k[kvbase + (size_t)j * DK + lq * 4];
        k4.x *= scale; k4.y *= scale; k4.z *= scale; k4.w *= scale;
        float p[G];
        #pragma unroll
        for (int g = 0; g < G; g++) {
            const float4 r4 = __ldcs((const float4*)&rq[rrow + (size_t)(g * (LL * DK) + j * DK) + lq * 4]);
            p[g] = q4[g].x * (k4.x + r4.x) + q4[g].y * (k4.y + r4.y)
                 + q4[g].z * (k4.z + r4.z) + q4[g].w * (k4.w + r4.w);
        }
        #pragma unroll
        for (int g = 0; g < G; g++) {
            p[g] += __shfl_down_sync(0xffffffffu, p[g], 8, 16);
            p[g] += __shfl_down_sync(0xffffffffu, p[g], 4, 16);
            p[g] += __shfl_down_sync(0xffffffffu, p[g], 2, 16);
            p[g] += __shfl_down_sync(0xffffffffu, p[g], 1, 16);
        }
        if (lq == 0) {
            #pragma unroll
            for (int g = 0; g < G; g++) sc[g][j] = p[g];
        }
    }
    __syncthreads();

    {
        const int r   = warp >> 1;
        const int sub = warp & 1;
        const int mbase = (b * LL + i0 + r) * LL + sub * 128 + lane;
        float s[4];
        #pragma unroll
        for (int k = 0; k < 4; k++) {
            float v = sc[r][sub * 128 + lane + 32 * k];
            if (mask[mbase + 32 * k] == 0) v = -1e9f;
            s[k] = v;
        }
        float m = fmaxf(fmaxf(s[0], s[1]), fmaxf(s[2], s[3]));
        #pragma unroll
        for (int off = 16; off > 0; off >>= 1)
            m = fmaxf(m, __shfl_xor_sync(0xffffffffu, m, off));
        if (lane == 0) wred[warp] = m;
        __syncthreads();
        const float rowmax = fmaxf(wred[2 * r], wred[2 * r + 1]);
        float e0v = __expf(s[0] - rowmax), e1v = __expf(s[1] - rowmax);
        float e2v = __expf(s[2] - rowmax), e3v = __expf(s[3] - rowmax);
        float sum = e0v + e1v + e2v + e3v;
        #pragma unroll
        for (int off = 16; off > 0; off >>= 1)
            sum += __shfl_xor_sync(0xffffffffu, sum, off);
        __syncthreads();
        if (lane == 0) wred[warp] = sum;
        __syncthreads();
        const float inv = 1.0f / (wred[2 * r] + wred[2 * r + 1]);
        sc[r][sub * 128 + lane +  0] = e0v * inv;
        sc[r][sub * 128 + lane + 32] = e1v * inv;
        sc[r][sub * 128 + lane + 64] = e2v * inv;
        sc[r][sub * 128 + lane + 96] = e3v * inv;
    }
    __syncthreads();

    float4 acc[G];
    #pragma unroll
    for (int g = 0; g < G; g++) acc[g] = make_float4(0.f, 0.f, 0.f, 0.f);

    #pragma unroll 3
    for (int it = 0; it < 16; it++) {
        const int j = it * 16 + warp * 2 + half;
        const float4 v4 = *(const float4*)&g_v[kvbase + (size_t)j * DK + lq * 4];
        #pragma unroll
        for (int g = 0; g < G; g++) {
            const float4 r4 = __ldcs((const float4*)&rv[rrow + (size_t)(g * (LL * DK) + j * DK) + lq * 4]);
            const float pj = sc[g][j];
            acc[g].x += pj * (v4.x + r4.x);
            acc[g].y += pj * (v4.y + r4.y);
            acc[g].z += pj * (v4.z + r4.z);
            acc[g].w += pj * (v4.w + r4.w);
        }
    }
    #pragma unroll
    for (int g = 0; g < G; g++)
        *(float4*)&cpart[warp * 2 + half][g][lq * 4] = acc[g];
    __syncthreads();

    {
        const int g = tid >> 6, d = tid & 63;
        float ssum = 0.f;
        #pragma unroll
        for (int p = 0; p < 16; p++) ssum += cpart[p][g][d];
        g_ctx[kvbase + (size_t)(i0 + g) * DK + d] = ssum;
    }
}

// ---------------------------------------------------------------------------
// Output projection (R12 fp32, unchanged): 32x64x32, 128 threads, 4x4/thread,
// double-buffered; gathers ctx; out = ctx @ Wo^T + bo.
// ---------------------------------------------------------------------------
#define PBK 32
#define NKT (DD / PBK)

__global__ void __launch_bounds__(128) out_kernel(
    const float* __restrict__ Wo, const float* __restrict__ bo,
    float* __restrict__ out)
{
    __shared__ float Xs[2][PBK][32 + 4];
    __shared__ float Ws[2][PBK][64 + 4];

    const int tid = threadIdx.x;
    const int tx = tid & 15;
    const int ty = tid >> 4;
    const int m0 = blockIdx.y * 32;
    const int n0 = blockIdx.x * 64;

    const int xr = tid >> 2, xc4 = tid & 3;
    const int wr0 = tid >> 1, wc4_0 = (tid & 1) * 2;

    const int mm = m0 + xr;
    const int bb = mm >> 8, l = mm & 255;
    const float* Wp = &Wo[(size_t)(n0 + wr0) * DD + wc4_0 * 4];

    float4 px0, px1, pw0, pw1, pw2, pw3;
    {
        int c0 = xc4 * 4;       int h0 = c0 >> 6, d0 = c0 & 63;
        int c1 = 16 + xc4 * 4;  int h1 = c1 >> 6, d1 = c1 & 63;
        px0 = *(const float4*)&g_ctx[((size_t)(bb * HH + h0) * LL + l) * DK + d0];
        px1 = *(const float4*)&g_ctx[((size_t)(bb * HH + h1) * LL + l) * DK + d1];
    }
    pw0 = *(const float4*)(Wp);
    pw1 = *(const float4*)(Wp + 4);
    pw2 = *(const float4*)(Wp + 16);
    pw3 = *(const float4*)(Wp + 20);

    float4 acc0 = {0,0,0,0}, acc1 = {0,0,0,0}, acc2 = {0,0,0,0}, acc3 = {0,0,0,0};

    #pragma unroll 1
    for (int t = 0; t < NKT; t++) {
        const int cur = t & 1;
        Xs[cur][xc4*4+0][xr] = px0.x; Xs[cur][xc4*4+1][xr] = px0.y;
        Xs[cur][xc4*4+2][xr] = px0.z; Xs[cur][xc4*4+3][xr] = px0.w;
        Xs[cur][16+xc4*4+0][xr] = px1.x; Xs[cur][16+xc4*4+1][xr] = px1.y;
        Xs[cur][16+xc4*4+2][xr] = px1.z; Xs[cur][16+xc4*4+3][xr] = px1.w;
        Ws[cur][wc4_0*4+0][wr0] = pw0.x; Ws[cur][wc4_0*4+1][wr0] = pw0.y;
        Ws[cur][wc4_0*4+2][wr0] = pw0.z; Ws[cur][wc4_0*4+3][wr0] = pw0.w;
        Ws[cur][wc4_0*4+4][wr0] = pw1.x; Ws[cur][wc4_0*4+5][wr0] = pw1.y;
        Ws[cur][wc4_0*4+6][wr0] = pw1.z; Ws[cur][wc4_0*4+7][wr0] = pw1.w;
        Ws[cur][16+wc4_0*4+0][wr0] = pw2.x; Ws[cur][16+wc4_0*4+1][wr0] = pw2.y;
        Ws[cur][16+wc4_0*4+2][wr0] = pw2.z; Ws[cur][16+wc4_0*4+3][wr0] = pw2.w;
        Ws[cur][16+wc4_0*4+4][wr0] = pw3.x; Ws[cur][16+wc4_0*4+5][wr0] = pw3.y;
        Ws[cur][16+wc4_0*4+6][wr0] = pw3.z; Ws[cur][16+wc4_0*4+7][wr0] = pw3.w;
        __syncthreads();

        if (t + 1 < NKT) {
            const int k0n = (t + 1) * PBK;
            int c0 = k0n + xc4 * 4;       int h0 = c0 >> 6, d0 = c0 & 63;
            int c1 = k0n + 16 + xc4 * 4;  int h1 = c1 >> 6, d1 = c1 & 63;
            px0 = *(const float4*)&g_ctx[((size_t)(bb * HH + h0) * LL + l) * DK + d0];
            px1 = *(const float4*)&g_ctx[((size_t)(bb * HH + h1) * LL + l) * DK + d1];
            pw0 = *(const float4*)(Wp + k0n);
            pw1 = *(const float4*)(Wp + k0n + 4);
            pw2 = *(const float4*)(Wp + k0n + 16);
            pw3 = *(const float4*)(Wp + k0n + 20);
        }

        #pragma unroll
        for (int kk = 0; kk < PBK; kk++) {
            float4 a = *(const float4*)&Xs[cur][kk][ty * 4];
            float4 b = *(const float4*)&Ws[cur][kk][tx * 4];
            acc0.x += a.x*b.x; acc0.y += a.x*b.y; acc0.z += a.x*b.z; acc0.w += a.x*b.w;
            acc1.x += a.y*b.x; acc1.y += a.y*b.y; acc1.z += a.y*b.z; acc1.w += a.y*b.w;
            acc2.x += a.z*b.x; acc2.y += a.z*b.y; acc2.z += a.z*b.z; acc2.w += a.z*b.w;
            acc3.x += a.w*b.x; acc3.y += a.w*b.y; acc3.z += a.w*b.z; acc3.w += a.w*b.w;
        }
        __syncthreads();
    }

    const int e0 = n0 + tx * 4;
    float4 b4 = *(const float4*)&bo[e0];
    float4 accs[4] = {acc0, acc1, acc2, acc3};
    #pragma unroll
    for (int i = 0; i < 4; i++) {
        int m = m0 + ty * 4 + i;
        float4 o;
        o.x = accs[i].x + b4.x; o.y = accs[i].y + b4.y;
        o.z = accs[i].z + b4.z; o.w = accs[i].w + b4.w;
        *(float4*)&out[(size_t)m * DD + e0] = o;
    }
}

extern "C" void kernel_launch(void* const* d_in, const int* in_sizes, int n_in,
                              void* d_out, int out_size)
{
    const float* query = (const float*)d_in[0];
    const float* key   = (const float*)d_in[1];
    const float* value = (const float*)d_in[2];
    const int*   mask  = (const int*)d_in[3];
    const float* rq    = (const float*)d_in[4];
    const float* rv    = (const float*)d_in[5];
    const float* Wq    = (const float*)d_in[6];
    const float* bq    = (const float*)d_in[7];
    const float* Wk    = (const float*)d_in[8];
    const float* bk    = (const float*)d_in[9];
    const float* Wv    = (const float*)d_in[10];
    const float* bv    = (const float*)d_in[11];
    const float* Wo    = (const float*)d_in[12];
    const float* bo    = (const float*)d_in[13];
    float* out = (float*)d_out;

    proj_kernel<<<dim3(DD / 64, (BB * LL) / 32, 3), 128>>>(
        query, key, value, Wq, bq, Wk, bk, Wv, bv);
    attn_kernel<<<dim3(LL / G, BH), 256>>>(mask, rq, rv);
    out_kernel<<<dim3(DD / 64, (BB * LL) / 32), 128>>>(Wo, bo, out);
}

// round 15
// speedup vs baseline: 1.0907x; 1.0319x over previous
#include <cuda_runtime.h>

#define HH 8
#define BB 2
#define LL 256
#define DD 512
#define DK 64
#define BH (BB*HH)

__device__ float g_q[BH*LL*DK];
__device__ float g_k[BH*LL*DK];
__device__ float g_v[BH*LL*DK];
__device__ float g_ctx[BH*LL*DK];

__device__ __forceinline__ unsigned f2tf32(float x) {
    unsigned r; asm("cvt.rna.tf32.f32 %0, %1;" : "=r"(r) : "f"(x)); return r;
}
__device__ __forceinline__ uint4 cvt4(float4 v) {
    uint4 u; u.x = f2tf32(v.x); u.y = f2tf32(v.y); u.z = f2tf32(v.z); u.w = f2tf32(v.w);
    return u;
}

#define KT 32
#define NCH (DD / KT)   // 16 k-chunks

// ---------------------------------------------------------------------------
// Fused Q/K/V projection, tf32 tensor cores. MT=32 x NT=64 x KT=32 tile,
// 256 threads = 8 warps (2M x 4N), warp tile 16x16 (2x m16n8k8 per k-step).
// Same tile/traffic as R12 but 2x warps -> 21 warps/SM for latency hiding.
// cvt to tf32 at smem-store time. Grid (8,16,3) = 384 CTAs.
// ---------------------------------------------------------------------------
__global__ void __launch_bounds__(256) proj_kernel(
    const float* __restrict__ q_in, const float* __restrict__ k_in,
    const float* __restrict__ v_in,
    const float* __restrict__ Wq, const float* __restrict__ bq,
    const float* __restrict__ Wk, const float* __restrict__ bk,
    const float* __restrict__ Wv, const float* __restrict__ bv)
{
    const int which = blockIdx.z;
    const float* X    = which == 0 ? q_in : (which == 1 ? k_in : v_in);
    const float* W    = which == 0 ? Wq   : (which == 1 ? Wk   : Wv);
    const float* bias = which == 0 ? bq   : (which == 1 ? bk   : bv);
    float*       Y    = which == 0 ? g_q  : (which == 1 ? g_k  : g_v);

    __shared__ unsigned Xs[2][32][KT + 4];
    __shared__ unsigned Ws[2][64][KT + 4];

    const int tid  = threadIdx.x;
    const int warp = tid >> 5;
    const int lane = tid & 31;
    const int wm = warp & 1;          // M tile (16 rows)
    const int wn = warp >> 1;         // N tile (16 cols, 0..3)
    const int g  = lane >> 2;
    const int t  = lane & 3;

    const int m0 = blockIdx.y * 32;
    const int n0 = blockIdx.x * 64;

    // loaders (256 thr): X 32x32 = 1024 fl -> 1 float4/thread;
    //                    W 64x32 = 2048 fl -> 2 float4/thread
    const int xr = tid >> 3, xc = tid & 7;           // X: row 0..31, quad 0..7
    const int wr = tid >> 2, wc = (tid & 3) * 2;     // W: row 0..63, quads wc, wc+1
    const float* Xp = &X[(size_t)(m0 + xr) * DD + xc * 4];
    const float* Wp = &W[(size_t)(n0 + wr) * DD + wc * 4];

    float4 px0 = *(const float4*)(Xp);
    float4 pw0 = *(const float4*)(Wp);
    float4 pw1 = *(const float4*)(Wp + 4);

    float c[2][4];
    #pragma unroll
    for (int j = 0; j < 2; j++)
        #pragma unroll
        for (int q = 0; q < 4; q++) c[j][q] = 0.f;

    #pragma unroll 1
    for (int ch = 0; ch < NCH; ch++) {
        const int cur = ch & 1;
        *(uint4*)&Xs[cur][xr][xc * 4]     = cvt4(px0);
        *(uint4*)&Ws[cur][wr][wc * 4]     = cvt4(pw0);
        *(uint4*)&Ws[cur][wr][wc * 4 + 4] = cvt4(pw1);
        __syncthreads();

        if (ch + 1 < NCH) {
            const int k0n = (ch + 1) * KT;
            px0 = *(const float4*)(Xp + k0n);
            pw0 = *(const float4*)(Wp + k0n);
            pw1 = *(const float4*)(Wp + k0n + 4);
        }

        const int ar = wm * 16;
        #pragma unroll
        for (int ks = 0; ks < 4; ks++) {
            const int K = ks * 8;
            const unsigned a0 = Xs[cur][ar + g][K + t];
            const unsigned a1 = Xs[cur][ar + 8 + g][K + t];
            const unsigned a2 = Xs[cur][ar + g][K + t + 4];
            const unsigned a3 = Xs[cur][ar + 8 + g][K + t + 4];
            #pragma unroll
            for (int j = 0; j < 2; j++) {
                const int nb = wn * 16 + j * 8;
                const unsigned b0 = Ws[cur][nb + g][K + t];
                const unsigned b1 = Ws[cur][nb + g][K + t + 4];
                asm volatile(
                    "mma.sync.aligned.m16n8k8.row.col.f32.tf32.tf32.f32 "
                    "{%0,%1,%2,%3}, {%4,%5,%6,%7}, {%8,%9}, {%0,%1,%2,%3};"
                    : "+f"(c[j][0]), "+f"(c[j][1]), "+f"(c[j][2]), "+f"(c[j][3])
                    : "r"(a0), "r"(a1), "r"(a2), "r"(a3), "r"(b0), "r"(b1));
            }
        }
        __syncthreads();
    }

    // Epilogue: scatter into [B*H, L, dk]; NT=64 aligned -> one head per CTA.
    const int h = n0 >> 6;
    const int row0 = m0 + wm * 16 + g;
    const int b0i = row0 >> 8, l0 = row0 & 255;
    const int row1 = row0 + 8;
    const int b1i = row1 >> 8, l1 = row1 & 255;
    #pragma unroll
    for (int j = 0; j < 2; j++) {
        const int col = n0 + wn * 16 + j * 8 + 2 * t;
        const int d = col & 63;
        const float bx = bias[col], by = bias[col + 1];
        *(float2*)&Y[((size_t)(b0i * HH + h) * LL + l0) * DK + d] =
            make_float2(c[j][0] + bx, c[j][1] + by);
        *(float2*)&Y[((size_t)(b1i * HH + h) * LL + l1) * DK + d] =
            make_float2(c[j][2] + bx, c[j][3] + by);
    }
}

// ---------------------------------------------------------------------------
// Attention core (R12 exact, unroll 2 — measured best): G=4 query rows per
// CTA; half-warp per j; rq/rv streamed __ldcs.
// ---------------------------------------------------------------------------
#define G 4
__global__ void __launch_bounds__(256) attn_kernel(
    const int* __restrict__ mask,
    const float* __restrict__ rq,
    const float* __restrict__ rv)
{
    const int i0 = blockIdx.x * G;
    const int bh = blockIdx.y;
    const int b  = bh >> 3;
    const int tid  = threadIdx.x;
    const int warp = tid >> 5;
    const int lane = tid & 31;
    const int half = lane >> 4;
    const int lq   = lane & 15;

    __shared__ float sc[G][LL];
    __shared__ float cpart[16][G][DK + 4];
    __shared__ float wred[8];

    const float scale = 0.125f;
    const size_t kvbase = (size_t)bh * LL * DK;
    const size_t rrow   = ((size_t)bh * LL + i0) * (size_t)(LL * DK);

    float4 q4[G];
    #pragma unroll
    for (int g = 0; g < G; g++)
        q4[g] = *(const float4*)&g_q[kvbase + (size_t)(i0 + g) * DK + lq * 4];

    #pragma unroll 2
    for (int it = 0; it < 16; it++) {
        const int j = it * 16 + warp * 2 + half;
        float4 k4 = *(const float4*)&g_k[kvbase + (size_t)j * DK + lq * 4];
        k4.x *= scale; k4.y *= scale; k4.z *= scale; k4.w *= scale;
        float p[G];
        #pragma unroll
        for (int g = 0; g < G; g++) {
            const float4 r4 = __ldcs((const float4*)&rq[rrow + (size_t)(g * (LL * DK) + j * DK) + lq * 4]);
            p[g] = q4[g].x * (k4.x + r4.x) + q4[g].y * (k4.y + r4.y)
                 + q4[g].z * (k4.z + r4.z) + q4[g].w * (k4.w + r4.w);
        }
        #pragma unroll
        for (int g = 0; g < G; g++) {
            p[g] += __shfl_down_sync(0xffffffffu, p[g], 8, 16);
            p[g] += __shfl_down_sync(0xffffffffu, p[g], 4, 16);
            p[g] += __shfl_down_sync(0xffffffffu, p[g], 2, 16);
            p[g] += __shfl_down_sync(0xffffffffu, p[g], 1, 16);
        }
        if (lq == 0) {
            #pragma unroll
            for (int g = 0; g < G; g++) sc[g][j] = p[g];
        }
    }
    __syncthreads();

    {
        const int r   = warp >> 1;
        const int sub = warp & 1;
        const int mbase = (b * LL + i0 + r) * LL + sub * 128 + lane;
        float s[4];
        #pragma unroll
        for (int k = 0; k < 4; k++) {
            float v = sc[r][sub * 128 + lane + 32 * k];
            if (mask[mbase + 32 * k] == 0) v = -1e9f;
            s[k] = v;
        }
        float m = fmaxf(fmaxf(s[0], s[1]), fmaxf(s[2], s[3]));
        #pragma unroll
        for (int off = 16; off > 0; off >>= 1)
            m = fmaxf(m, __shfl_xor_sync(0xffffffffu, m, off));
        if (lane == 0) wred[warp] = m;
        __syncthreads();
        const float rowmax = fmaxf(wred[2 * r], wred[2 * r + 1]);
        float e0v = __expf(s[0] - rowmax), e1v = __expf(s[1] - rowmax);
        float e2v = __expf(s[2] - rowmax), e3v = __expf(s[3] - rowmax);
        float sum = e0v + e1v + e2v + e3v;
        #pragma unroll
        for (int off = 16; off > 0; off >>= 1)
            sum += __shfl_xor_sync(0xffffffffu, sum, off);
        __syncthreads();
        if (lane == 0) wred[warp] = sum;
        __syncthreads();
        const float inv = 1.0f / (wred[2 * r] + wred[2 * r + 1]);
        sc[r][sub * 128 + lane +  0] = e0v * inv;
        sc[r][sub * 128 + lane + 32] = e1v * inv;
        sc[r][sub * 128 + lane + 64] = e2v * inv;
        sc[r][sub * 128 + lane + 96] = e3v * inv;
    }
    __syncthreads();

    float4 acc[G];
    #pragma unroll
    for (int g = 0; g < G; g++) acc[g] = make_float4(0.f, 0.f, 0.f, 0.f);

    #pragma unroll 2
    for (int it = 0; it < 16; it++) {
        const int j = it * 16 + warp * 2 + half;
        const float4 v4 = *(const float4*)&g_v[kvbase + (size_t)j * DK + lq * 4];
        #pragma unroll
        for (int g = 0; g < G; g++) {
            const float4 r4 = __ldcs((const float4*)&rv[rrow + (size_t)(g * (LL * DK) + j * DK) + lq * 4]);
            const float pj = sc[g][j];
            acc[g].x += pj * (v4.x + r4.x);
            acc[g].y += pj * (v4.y + r4.y);
            acc[g].z += pj * (v4.z + r4.z);
            acc[g].w += pj * (v4.w + r4.w);
        }
    }
    #pragma unroll
    for (int g = 0; g < G; g++)
        *(float4*)&cpart[warp * 2 + half][g][lq * 4] = acc[g];
    __syncthreads();

    {
        const int g = tid >> 6, d = tid & 63;
        float ssum = 0.f;
        #pragma unroll
        for (int p = 0; p < 16; p++) ssum += cpart[p][g][d];
        g_ctx[kvbase + (size_t)(i0 + g) * DK + d] = ssum;
    }
}

// ---------------------------------------------------------------------------
// Output projection (R12 fp32, unchanged): 32x64x32, 128 threads, 4x4/thread,
// double-buffered; gathers ctx; out = ctx @ Wo^T + bo.
// ---------------------------------------------------------------------------
#define PBK 32
#define NKT (DD / PBK)

__global__ void __launch_bounds__(128) out_kernel(
    const float* __restrict__ Wo, const float* __restrict__ bo,
    float* __restrict__ out)
{
    __shared__ float Xs[2][PBK][32 + 4];
    __shared__ float Ws[2][PBK][64 + 4];

    const int tid = threadIdx.x;
    const int tx = tid & 15;
    const int ty = tid >> 4;
    const int m0 = blockIdx.y * 32;
    const int n0 = blockIdx.x * 64;

    const int xr = tid >> 2, xc4 = tid & 3;
    const int wr0 = tid >> 1, wc4_0 = (tid & 1) * 2;

    const int mm = m0 + xr;
    const int bb = mm >> 8, l = mm & 255;
    const float* Wp = &Wo[(size_t)(n0 + wr0) * DD + wc4_0 * 4];

    float4 px0, px1, pw0, pw1, pw2, pw3;
    {
        int c0 = xc4 * 4;       int h0 = c0 >> 6, d0 = c0 & 63;
        int c1 = 16 + xc4 * 4;  int h1 = c1 >> 6, d1 = c1 & 63;
        px0 = *(const float4*)&g_ctx[((size_t)(bb * HH + h0) * LL + l) * DK + d0];
        px1 = *(const float4*)&g_ctx[((size_t)(bb * HH + h1) * LL + l) * DK + d1];
    }
    pw0 = *(const float4*)(Wp);
    pw1 = *(const float4*)(Wp + 4);
    pw2 = *(const float4*)(Wp + 16);
    pw3 = *(const float4*)(Wp + 20);

    float4 acc0 = {0,0,0,0}, acc1 = {0,0,0,0}, acc2 = {0,0,0,0}, acc3 = {0,0,0,0};

    #pragma unroll 1
    for (int t = 0; t < NKT; t++) {
        const int cur = t & 1;
        Xs[cur][xc4*4+0][xr] = px0.x; Xs[cur][xc4*4+1][xr] = px0.y;
        Xs[cur][xc4*4+2][xr] = px0.z; Xs[cur][xc4*4+3][xr] = px0.w;
        Xs[cur][16+xc4*4+0][xr] = px1.x; Xs[cur][16+xc4*4+1][xr] = px1.y;
        Xs[cur][16+xc4*4+2][xr] = px1.z; Xs[cur][16+xc4*4+3][xr] = px1.w;
        Ws[cur][wc4_0*4+0][wr0] = pw0.x; Ws[cur][wc4_0*4+1][wr0] = pw0.y;
        Ws[cur][wc4_0*4+2][wr0] = pw0.z; Ws[cur][wc4_0*4+3][wr0] = pw0.w;
        Ws[cur][wc4_0*4+4][wr0] = pw1.x; Ws[cur][wc4_0*4+5][wr0] = pw1.y;
        Ws[cur][wc4_0*4+6][wr0] = pw1.z; Ws[cur][wc4_0*4+7][wr0] = pw1.w;
        Ws[cur][16+wc4_0*4+0][wr0] = pw2.x; Ws[cur][16+wc4_0*4+1][wr0] = pw2.y;
        Ws[cur][16+wc4_0*4+2][wr0] = pw2.z; Ws[cur][16+wc4_0*4+3][wr0] = pw2.w;
        Ws[cur][16+wc4_0*4+4][wr0] = pw3.x; Ws[cur][16+wc4_0*4+5][wr0] = pw3.y;
        Ws[cur][16+wc4_0*4+6][wr0] = pw3.z; Ws[cur][16+wc4_0*4+7][wr0] = pw3.w;
        __syncthreads();

        if (t + 1 < NKT) {
            const int k0n = (t + 1) * PBK;
            int c0 = k0n + xc4 * 4;       int h0 = c0 >> 6, d0 = c0 & 63;
            int c1 = k0n + 16 + xc4 * 4;  int h1 = c1 >> 6, d1 = c1 & 63;
            px0 = *(const float4*)&g_ctx[((size_t)(bb * HH + h0) * LL + l) * DK + d0];
            px1 = *(const float4*)&g_ctx[((size_t)(bb * HH + h1) * LL + l) * DK + d1];
            pw0 = *(const float4*)(Wp + k0n);
            pw1 = *(const float4*)(Wp + k0n + 4);
            pw2 = *(const float4*)(Wp + k0n + 16);
            pw3 = *(const float4*)(Wp + k0n + 20);
        }

        #pragma unroll
        for (int kk = 0; kk < PBK; kk++) {
            float4 a = *(const float4*)&Xs[cur][kk][ty * 4];
            float4 b = *(const float4*)&Ws[cur][kk][tx * 4];
            acc0.x += a.x*b.x; acc0.y += a.x*b.y; acc0.z += a.x*b.z; acc0.w += a.x*b.w;
            acc1.x += a.y*b.x; acc1.y += a.y*b.y; acc1.z += a.y*b.z; acc1.w += a.y*b.w;
            acc2.x += a.z*b.x; acc2.y += a.z*b.y; acc2.z += a.z*b.z; acc2.w += a.z*b.w;
            acc3.x += a.w*b.x; acc3.y += a.w*b.y; acc3.z += a.w*b.z; acc3.w += a.w*b.w;
        }
        __syncthreads();
    }

    const int e0 = n0 + tx * 4;
    float4 b4 = *(const float4*)&bo[e0];
    float4 accs[4] = {acc0, acc1, acc2, acc3};
    #pragma unroll
    for (int i = 0; i < 4; i++) {
        int m = m0 + ty * 4 + i;
        float4 o;
        o.x = accs[i].x + b4.x; o.y = accs[i].y + b4.y;
        o.z = accs[i].z + b4.z; o.w = accs[i].w + b4.w;
        *(float4*)&out[(size_t)m * DD + e0] = o;
    }
}

extern "C" void kernel_launch(void* const* d_in, const int* in_sizes, int n_in,
                              void* d_out, int out_size)
{
    const float* query = (const float*)d_in[0];
    const float* key   = (const float*)d_in[1];
    const float* value = (const float*)d_in[2];
    const int*   mask  = (const int*)d_in[3];
    const float* rq    = (const float*)d_in[4];
    const float* rv    = (const float*)d_in[5];
    const float* Wq    = (const float*)d_in[6];
    const float* bq    = (const float*)d_in[7];
    const float* Wk    = (const float*)d_in[8];
    const float* bk    = (const float*)d_in[9];
    const float* Wv    = (const float*)d_in[10];
    const float* bv    = (const float*)d_in[11];
    const float* Wo    = (const float*)d_in[12];
    const float* bo    = (const float*)d_in[13];
    float* out = (float*)d_out;

    proj_kernel<<<dim3(DD / 64, (BB * LL) / 32, 3), 256>>>(
        query, key, value, Wq, bq, Wk, bk, Wv, bv);
    attn_kernel<<<dim3(LL / G, BH), 256>>>(mask, rq, rv);
    out_kernel<<<dim3(DD / 64, (BB * LL) / 32), 128>>>(Wo, bo, out);
}

// round 17
// speedup vs baseline: 1.1319x; 1.0378x over previous
#include <cuda_runtime.h>

#define HH 8
#define BB 2
#define LL 256
#define DD 512
#define DK 64
#define BH (BB*HH)

__device__ float g_q[BH*LL*DK];
__device__ float g_k[BH*LL*DK];
__device__ float g_v[BH*LL*DK];
__device__ float g_ctx[BH*LL*DK];

__device__ __forceinline__ unsigned f2tf32(float x) {
    unsigned r; asm("cvt.rna.tf32.f32 %0, %1;" : "=r"(r) : "f"(x)); return r;
}
__device__ __forceinline__ uint4 cvt4(float4 v) {
    uint4 u; u.x = f2tf32(v.x); u.y = f2tf32(v.y); u.z = f2tf32(v.z); u.w = f2tf32(v.w);
    return u;
}

#define KT 32
#define NCH (DD / KT)   // 16 k-chunks

// ---------------------------------------------------------------------------
// Fused Q/K/V projection, tf32 tensor cores (R15 exact — measured best).
// MT=32 x NT=64 x KT=32 tile, 256 threads = 8 warps (2M x 4N), warp tile
// 16x16. cvt at smem-store time. Grid (8,16,3) = 384 CTAs.
// ---------------------------------------------------------------------------
__global__ void __launch_bounds__(256) proj_kernel(
    const float* __restrict__ q_in, const float* __restrict__ k_in,
    const float* __restrict__ v_in,
    const float* __restrict__ Wq, const float* __restrict__ bq,
    const float* __restrict__ Wk, const float* __restrict__ bk,
    const float* __restrict__ Wv, const float* __restrict__ bv)
{
    const int which = blockIdx.z;
    const float* X    = which == 0 ? q_in : (which == 1 ? k_in : v_in);
    const float* W    = which == 0 ? Wq   : (which == 1 ? Wk   : Wv);
    const float* bias = which == 0 ? bq   : (which == 1 ? bk   : bv);
    float*       Y    = which == 0 ? g_q  : (which == 1 ? g_k  : g_v);

    __shared__ unsigned Xs[2][32][KT + 4];
    __shared__ unsigned Ws[2][64][KT + 4];

    const int tid  = threadIdx.x;
    const int warp = tid >> 5;
    const int lane = tid & 31;
    const int wm = warp & 1;
    const int wn = warp >> 1;
    const int g  = lane >> 2;
    const int t  = lane & 3;

    const int m0 = blockIdx.y * 32;
    const int n0 = blockIdx.x * 64;

    const int xr = tid >> 3, xc = tid & 7;
    const int wr = tid >> 2, wc = (tid & 3) * 2;
    const float* Xp = &X[(size_t)(m0 + xr) * DD + xc * 4];
    const float* Wp = &W[(size_t)(n0 + wr) * DD + wc * 4];

    float4 px0 = *(const float4*)(Xp);
    float4 pw0 = *(const float4*)(Wp);
    float4 pw1 = *(const float4*)(Wp + 4);

    float c[2][4];
    #pragma unroll
    for (int j = 0; j < 2; j++)
        #pragma unroll
        for (int q = 0; q < 4; q++) c[j][q] = 0.f;

    #pragma unroll 1
    for (int ch = 0; ch < NCH; ch++) {
        const int cur = ch & 1;
        *(uint4*)&Xs[cur][xr][xc * 4]     = cvt4(px0);
        *(uint4*)&Ws[cur][wr][wc * 4]     = cvt4(pw0);
        *(uint4*)&Ws[cur][wr][wc * 4 + 4] = cvt4(pw1);
        __syncthreads();

        if (ch + 1 < NCH) {
            const int k0n = (ch + 1) * KT;
            px0 = *(const float4*)(Xp + k0n);
            pw0 = *(const float4*)(Wp + k0n);
            pw1 = *(const float4*)(Wp + k0n + 4);
        }

        const int ar = wm * 16;
        #pragma unroll
        for (int ks = 0; ks < 4; ks++) {
            const int K = ks * 8;
            const unsigned a0 = Xs[cur][ar + g][K + t];
            const unsigned a1 = Xs[cur][ar + 8 + g][K + t];
            const unsigned a2 = Xs[cur][ar + g][K + t + 4];
            const unsigned a3 = Xs[cur][ar + 8 + g][K + t + 4];
            #pragma unroll
            for (int j = 0; j < 2; j++) {
                const int nb = wn * 16 + j * 8;
                const unsigned b0 = Ws[cur][nb + g][K + t];
                const unsigned b1 = Ws[cur][nb + g][K + t + 4];
                asm volatile(
                    "mma.sync.aligned.m16n8k8.row.col.f32.tf32.tf32.f32 "
                    "{%0,%1,%2,%3}, {%4,%5,%6,%7}, {%8,%9}, {%0,%1,%2,%3};"
                    : "+f"(c[j][0]), "+f"(c[j][1]), "+f"(c[j][2]), "+f"(c[j][3])
                    : "r"(a0), "r"(a1), "r"(a2), "r"(a3), "r"(b0), "r"(b1));
            }
        }
        __syncthreads();
    }

    const int h = n0 >> 6;
    const int row0 = m0 + wm * 16 + g;
    const int b0i = row0 >> 8, l0 = row0 & 255;
    const int row1 = row0 + 8;
    const int b1i = row1 >> 8, l1 = row1 & 255;
    #pragma unroll
    for (int j = 0; j < 2; j++) {
        const int col = n0 + wn * 16 + j * 8 + 2 * t;
        const int d = col & 63;
        const float bx = bias[col], by = bias[col + 1];
        *(float2*)&Y[((size_t)(b0i * HH + h) * LL + l0) * DK + d] =
            make_float2(c[j][0] + bx, c[j][1] + by);
        *(float2*)&Y[((size_t)(b1i * HH + h) * LL + l1) * DK + d] =
            make_float2(c[j][2] + bx, c[j][3] + by);
    }
}

// ---------------------------------------------------------------------------
// Attention core (R12 exact, unroll 2 — measured best): G=4 query rows per
// CTA; half-warp per j; rq/rv streamed __ldcs.
// ---------------------------------------------------------------------------
#define G 4
__global__ void __launch_bounds__(256) attn_kernel(
    const int* __restrict__ mask,
    const float* __restrict__ rq,
    const float* __restrict__ rv)
{
    const int i0 = blockIdx.x * G;
    const int bh = blockIdx.y;
    const int b  = bh >> 3;
    const int tid  = threadIdx.x;
    const int warp = tid >> 5;
    const int lane = tid & 31;
    const int half = lane >> 4;
    const int lq   = lane & 15;

    __shared__ float sc[G][LL];
    __shared__ float cpart[16][G][DK + 4];
    __shared__ float wred[8];

    const float scale = 0.125f;
    const size_t kvbase = (size_t)bh * LL * DK;
    const size_t rrow   = ((size_t)bh * LL + i0) * (size_t)(LL * DK);

    float4 q4[G];
    #pragma unroll
    for (int g = 0; g < G; g++)
        q4[g] = *(const float4*)&g_q[kvbase + (size_t)(i0 + g) * DK + lq * 4];

    #pragma unroll 2
    for (int it = 0; it < 16; it++) {
        const int j = it * 16 + warp * 2 + half;
        float4 k4 = *(const float4*)&g_k[kvbase + (size_t)j * DK + lq * 4];
        k4.x *= scale; k4.y *= scale; k4.z *= scale; k4.w *= scale;
        float p[G];
        #pragma unroll
        for (int g = 0; g < G; g++) {
            const float4 r4 = __ldcs((const float4*)&rq[rrow + (size_t)(g * (LL * DK) + j * DK) + lq * 4]);
            p[g] = q4[g].x * (k4.x + r4.x) + q4[g].y * (k4.y + r4.y)
                 + q4[g].z * (k4.z + r4.z) + q4[g].w * (k4.w + r4.w);
        }
        #pragma unroll
        for (int g = 0; g < G; g++) {
            p[g] += __shfl_down_sync(0xffffffffu, p[g], 8, 16);
            p[g] += __shfl_down_sync(0xffffffffu, p[g], 4, 16);
            p[g] += __shfl_down_sync(0xffffffffu, p[g], 2, 16);
            p[g] += __shfl_down_sync(0xffffffffu, p[g], 1, 16);
        }
        if (lq == 0) {
            #pragma unroll
            for (int g = 0; g < G; g++) sc[g][j] = p[g];
        }
    }
    __syncthreads();

    {
        const int r   = warp >> 1;
        const int sub = warp & 1;
        const int mbase = (b * LL + i0 + r) * LL + sub * 128 + lane;
        float s[4];
        #pragma unroll
        for (int k = 0; k < 4; k++) {
            float v = sc[r][sub * 128 + lane + 32 * k];
            if (mask[mbase + 32 * k] == 0) v = -1e9f;
            s[k] = v;
        }
        float m = fmaxf(fmaxf(s[0], s[1]), fmaxf(s[2], s[3]));
        #pragma unroll
        for (int off = 16; off > 0; off >>= 1)
            m = fmaxf(m, __shfl_xor_sync(0xffffffffu, m, off));
        if (lane == 0) wred[warp] = m;
        __syncthreads();
        const float rowmax = fmaxf(wred[2 * r], wred[2 * r + 1]);
        float e0v = __expf(s[0] - rowmax), e1v = __expf(s[1] - rowmax);
        float e2v = __expf(s[2] - rowmax), e3v = __expf(s[3] - rowmax);
        float sum = e0v + e1v + e2v + e3v;
        #pragma unroll
        for (int off = 16; off > 0; off >>= 1)
            sum += __shfl_xor_sync(0xffffffffu, sum, off);
        __syncthreads();
        if (lane == 0) wred[warp] = sum;
        __syncthreads();
        const float inv = 1.0f / (wred[2 * r] + wred[2 * r + 1]);
        sc[r][sub * 128 + lane +  0] = e0v * inv;
        sc[r][sub * 128 + lane + 32] = e1v * inv;
        sc[r][sub * 128 + lane + 64] = e2v * inv;
        sc[r][sub * 128 + lane + 96] = e3v * inv;
    }
    __syncthreads();

    float4 acc[G];
    #pragma unroll
    for (int g = 0; g < G; g++) acc[g] = make_float4(0.f, 0.f, 0.f, 0.f);

    #pragma unroll 2
    for (int it = 0; it < 16; it++) {
        const int j = it * 16 + warp * 2 + half;
        const float4 v4 = *(const float4*)&g_v[kvbase + (size_t)j * DK + lq * 4];
        #pragma unroll
        for (int g = 0; g < G; g++) {
            const float4 r4 = __ldcs((const float4*)&rv[rrow + (size_t)(g * (LL * DK) + j * DK) + lq * 4]);
            const float pj = sc[g][j];
            acc[g].x += pj * (v4.x + r4.x);
            acc[g].y += pj * (v4.y + r4.y);
            acc[g].z += pj * (v4.z + r4.z);
            acc[g].w += pj * (v4.w + r4.w);
        }
    }
    #pragma unroll
    for (int g = 0; g < G; g++)
        *(float4*)&cpart[warp * 2 + half][g][lq * 4] = acc[g];
    __syncthreads();

    {
        const int g = tid >> 6, d = tid & 63;
        float ssum = 0.f;
        #pragma unroll
        for (int p = 0; p < 16; p++) ssum += cpart[p][g][d];
        g_ctx[kvbase + (size_t)(i0 + g) * DK + d] = ssum;
    }
}

// ---------------------------------------------------------------------------
// Output projection, tf32 tensor cores (R15 template). MT=32 x NT=64 x KT=32,
// 256 threads = 8 warps (2M x 4N), warp tile 16x16, double-buffered,
// cvt at store. Gathers ctx [B*H, L, dk]; out = ctx @ Wo^T + bo.
// Grid (8,16) = 128 CTAs.
// ---------------------------------------------------------------------------
__global__ void __launch_bounds__(256) out_kernel(
    const float* __restrict__ Wo, const float* __restrict__ bo,
    float* __restrict__ out)
{
    __shared__ unsigned Xs[2][32][KT + 4];
    __shared__ unsigned Ws[2][64][KT + 4];

    const int tid  = threadIdx.x;
    const int warp = tid >> 5;
    const int lane = tid & 31;
    const int wm = warp & 1;
    const int wn = warp >> 1;
    const int g  = lane >> 2;
    const int t  = lane & 3;

    const int m0 = blockIdx.y * 32;
    const int n0 = blockIdx.x * 64;

    // loaders: X (ctx gather) 32x32 -> 1 float4/thread; W 64x32 -> 2/thread
    const int xr = tid >> 3, xc = tid & 7;
    const int wr = tid >> 2, wc = (tid & 3) * 2;
    const int mm = m0 + xr;
    const int bb = mm >> 8, l = mm & 255;
    const float* Wp = &Wo[(size_t)(n0 + wr) * DD + wc * 4];

    float4 px0, pw0, pw1;
    {
        int c0 = xc * 4;                 // k0 = 0; float4 stays within a head
        int h0 = c0 >> 6, d0 = c0 & 63;
        px0 = *(const float4*)&g_ctx[((size_t)(bb * HH + h0) * LL + l) * DK + d0];
    }
    pw0 = *(const float4*)(Wp);
    pw1 = *(const float4*)(Wp + 4);

    float c[2][4];
    #pragma unroll
    for (int j = 0; j < 2; j++)
        #pragma unroll
        for (int q = 0; q < 4; q++) c[j][q] = 0.f;

    #pragma unroll 1
    for (int ch = 0; ch < NCH; ch++) {
        const int cur = ch & 1;
        *(uint4*)&Xs[cur][xr][xc * 4]     = cvt4(px0);
        *(uint4*)&Ws[cur][wr][wc * 4]     = cvt4(pw0);
        *(uint4*)&Ws[cur][wr][wc * 4 + 4] = cvt4(pw1);
        __syncthreads();

        if (ch + 1 < NCH) {
            const int k0n = (ch + 1) * KT;
            int c0 = k0n + xc * 4;
            int h0 = c0 >> 6, d0 = c0 & 63;
            px0 = *(const float4*)&g_ctx[((size_t)(bb * HH + h0) * LL + l) * DK + d0];
            pw0 = *(const float4*)(Wp + k0n);
            pw1 = *(const float4*)(Wp + k0n + 4);
        }

        const int ar = wm * 16;
        #pragma unroll
        for (int ks = 0; ks < 4; ks++) {
            const int K = ks * 8;
            const unsigned a0 = Xs[cur][ar + g][K + t];
            const unsigned a1 = Xs[cur][ar + 8 + g][K + t];
            const unsigned a2 = Xs[cur][ar + g][K + t + 4];
            const unsigned a3 = Xs[cur][ar + 8 + g][K + t + 4];
            #pragma unroll
            for (int j = 0; j < 2; j++) {
                const int nb = wn * 16 + j * 8;
                const unsigned b0 = Ws[cur][nb + g][K + t];
                const unsigned b1 = Ws[cur][nb + g][K + t + 4];
                asm volatile(
                    "mma.sync.aligned.m16n8k8.row.col.f32.tf32.tf32.f32 "
                    "{%0,%1,%2,%3}, {%4,%5,%6,%7}, {%8,%9}, {%0,%1,%2,%3};"
                    : "+f"(c[j][0]), "+f"(c[j][1]), "+f"(c[j][2]), "+f"(c[j][3])
                    : "r"(a0), "r"(a1), "r"(a2), "r"(a3), "r"(b0), "r"(b1));
            }
        }
        __syncthreads();
    }

    const int row0 = m0 + wm * 16 + g;
    const int row1 = row0 + 8;
    #pragma unroll
    for (int j = 0; j < 2; j++) {
        const int col = n0 + wn * 16 + j * 8 + 2 * t;
        const float bx = bo[col], by = bo[col + 1];
        *(float2*)&out[(size_t)row0 * DD + col] = make_float2(c[j][0] + bx, c[j][1] + by);
        *(float2*)&out[(size_t)row1 * DD + col] = make_float2(c[j][2] + bx, c[j][3] + by);
    }
}

extern "C" void kernel_launch(void* const* d_in, const int* in_sizes, int n_in,
                              void* d_out, int out_size)
{
    const float* query = (const float*)d_in[0];
    const float* key   = (const float*)d_in[1];
    const float* value = (const float*)d_in[2];
    const int*   mask  = (const int*)d_in[3];
    const float* rq    = (const float*)d_in[4];
    const float* rv    = (const float*)d_in[5];
    const float* Wq    = (const float*)d_in[6];
    const float* bq    = (const float*)d_in[7];
    const float* Wk    = (const float*)d_in[8];
    const float* bk    = (const float*)d_in[9];
    const float* Wv    = (const float*)d_in[10];
    const float* bv    = (const float*)d_in[11];
    const float* Wo    = (const float*)d_in[12];
    const float* bo    = (const float*)d_in[13];
    float* out = (float*)d_out;

    proj_kernel<<<dim3(DD / 64, (BB * LL) / 32, 3), 256>>>(
        query, key, value, Wq, bq, Wk, bk, Wv, bv);
    attn_kernel<<<dim3(LL / G, BH), 256>>>(mask, rq, rv);
    out_kernel<<<dim3(DD / 64, (BB * LL) / 32), 256>>>(Wo, bo, out);
}